// round 3
// baseline (speedup 1.0000x reference)
#include <cuda_runtime.h>
#include <cstdint>

// Problem constants
#define BATCH   8
#define NPTS    200000
#define NCH     32
#define RES     128
#define RR      (RES * RES)       // 16384
#define NPLANES 3
#define NBP     (BATCH * NPLANES) // 24

// Scratch accumulators, channel-contiguous [bp][bin][c] (128B bins).
// Zero-initialized at module load; finalize_kernel re-zeros after consuming,
// so every launch (correctness call + each graph replay) starts from zeros.
__device__ __align__(128) float g_acc[(size_t)NBP * RR * NCH];
__device__ __align__(128) float g_cnt[(size_t)NBP * RR];

__device__ __forceinline__ void red_add_v4(float* addr, float a, float b, float c, float d) {
    asm volatile("red.global.add.v4.f32 [%0], {%1, %2, %3, %4};"
                 :: "l"(addr), "f"(a), "f"(b), "f"(c), "f"(d) : "memory");
}
__device__ __forceinline__ void red_add_f32(float* addr, float v) {
    asm volatile("red.global.add.f32 [%0], %1;" :: "l"(addr), "f"(v) : "memory");
}

// ---------------------------------------------------------------------------
// Scatter: FOUR threads per point (thread = point*4 + q, q in 0..3).
// Lane q handles channels {q*4..q*4+3} and {16+q*4..16+q*4+3}. Within each
// red.v4 instruction, a point's 4 lanes write 64B contiguous in its 128B bin,
// so the LSU merges them into 2 L2 sectors (vs 8 when one lane walks the
// whole bin alone). Feature loads stay sector-coalesced: for a fixed channel,
// the 8 lanes of a q-group read 8 consecutive n (32B sector).
// ---------------------------------------------------------------------------
__global__ void __launch_bounds__(256) scatter_kernel(const float* __restrict__ xyz,
                                                      const float* __restrict__ feat) {
    const int tid = blockIdx.x * 256 + threadIdx.x;
    const int gid = tid >> 2;              // point id over all batches
    if (gid >= BATCH * NPTS) return;
    const int q = tid & 3;                 // channel quarter
    const int b = gid / NPTS;
    const int n = gid - b * NPTS;

    // xyz layout (B, N, 3); the 4 lanes of a point read the same 12B (sector broadcast)
    const float* p = xyz + (size_t)gid * 3;
    const float px = p[0], py = p[1], pz = p[2];

    // Mirror reference math exactly:
    //   xyz_norm = (p+1)/2 - 0.5 ; u = xyz_norm/(1+eps) + 0.5 ; clip [0, 1-eps] ; floor(u*128)
    const float DEN = 1.0f + 1e-5f;
    const float CLMP = 1.0f - 1e-5f;
    auto bin_of = [&](float v) -> int {
        float u = ((v + 1.0f) * 0.5f - 0.5f) / DEN + 0.5f;
        u = fminf(fmaxf(u, 0.0f), CLMP);
        return (int)(u * (float)RES);
    };
    const int ix = bin_of(px);
    const int iy = bin_of(py);
    const int iz = bin_of(pz);

    // plane dims: xy=(0,1), yz=(1,2), xz=(0,2); lin = idx[d0] + R*idx[d1]
    const int lin0 = ix + RES * iy;   // xy
    const int lin1 = iy + RES * iz;   // yz
    const int lin2 = ix + RES * iz;   // xz

    const int bp = b * NPLANES;
    if (q == 0) {
        red_add_f32(&g_cnt[(size_t)(bp + 0) * RR + lin0], 1.0f);
        red_add_f32(&g_cnt[(size_t)(bp + 1) * RR + lin1], 1.0f);
        red_add_f32(&g_cnt[(size_t)(bp + 2) * RR + lin2], 1.0f);
    }

    // This lane's 8 channels: lo = q*4..q*4+3, hi = 16+q*4..16+q*4+3
    const int c_lo = q * 4;
    const int c_hi = 16 + q * 4;
    const float* f = feat + (size_t)b * NCH * NPTS + n;

    const float l0 = f[(size_t)(c_lo + 0) * NPTS];
    const float l1 = f[(size_t)(c_lo + 1) * NPTS];
    const float l2 = f[(size_t)(c_lo + 2) * NPTS];
    const float l3 = f[(size_t)(c_lo + 3) * NPTS];
    const float h0 = f[(size_t)(c_hi + 0) * NPTS];
    const float h1 = f[(size_t)(c_hi + 1) * NPTS];
    const float h2 = f[(size_t)(c_hi + 2) * NPTS];
    const float h3 = f[(size_t)(c_hi + 3) * NPTS];

    float* a0 = g_acc + ((size_t)(bp + 0) * RR + lin0) * NCH;
    float* a1 = g_acc + ((size_t)(bp + 1) * RR + lin1) * NCH;
    float* a2 = g_acc + ((size_t)(bp + 2) * RR + lin2) * NCH;

    red_add_v4(a0 + c_lo, l0, l1, l2, l3);
    red_add_v4(a0 + c_hi, h0, h1, h2, h3);
    red_add_v4(a1 + c_lo, l0, l1, l2, l3);
    red_add_v4(a1 + c_hi, h0, h1, h2, h3);
    red_add_v4(a2 + c_lo, l0, l1, l2, l3);
    red_add_v4(a2 + c_hi, h0, h1, h2, h3);
}

// ---------------------------------------------------------------------------
// Finalize: transpose [bin][c] -> [c][bin] via padded smem, divide by
// max(count,1), AND re-zero the scratch it consumed (replaces zero_kernel).
// Block = 256 threads handles 128 bins of one (b,plane).
// ---------------------------------------------------------------------------
__global__ void __launch_bounds__(256) finalize_kernel(float* __restrict__ out) {
    __shared__ float s[128 * 33];     // pad to 33 to avoid bank conflicts
    __shared__ float sinv[128];

    const int tiles_per_bp = RR / 128;             // 128
    const int bp   = blockIdx.x / tiles_per_bp;    // 0..23
    const int tile = blockIdx.x % tiles_per_bp;    // 0..127
    const int bin0 = tile * 128;

    // Coalesced load of 128 bins x 32 channels, then re-zero what we read.
    float* accbase = g_acc + ((size_t)bp * RR + bin0) * NCH;
    for (int j = threadIdx.x; j < 128 * NCH; j += 256) {
        const int i = j >> 5;       // bin within tile
        const int c = j & 31;       // channel
        s[i * 33 + c] = accbase[j];
        accbase[j] = 0.0f;
    }
    for (int i = threadIdx.x; i < 128; i += 256) {
        float* cp = g_cnt + (size_t)bp * RR + bin0 + i;
        sinv[i] = 1.0f / fmaxf(*cp, 1.0f);
        *cp = 0.0f;
    }
    __syncthreads();

    // Coalesced store: out[(bp*C + c)*RR + bin0 + i]
    float* ob = out + (size_t)bp * NCH * RR + bin0;
    for (int j = threadIdx.x; j < 128 * NCH; j += 256) {
        const int c = j >> 7;       // channel
        const int i = j & 127;      // bin within tile
        ob[(size_t)c * RR + i] = s[i * 33 + c] * sinv[i];
    }
}

// ---------------------------------------------------------------------------
extern "C" void kernel_launch(void* const* d_in, const int* in_sizes, int n_in,
                              void* d_out, int out_size) {
    const float* xyz  = (const float*)d_in[0];  // (B, N, 3)
    const float* feat = (const float*)d_in[1];  // (B, C, N)
    float* out = (float*)d_out;                 // (B, 3, C, R, R)

    const int nthreads = BATCH * NPTS * 4;      // 4 lanes per point
    scatter_kernel<<<(nthreads + 255) / 256, 256>>>(xyz, feat);
    finalize_kernel<<<NBP * (RR / 128), 256>>>(out);
}

// round 4
// speedup vs baseline: 1.0053x; 1.0053x over previous
#include <cuda_runtime.h>
#include <cstdint>

// Problem constants
#define BATCH   8
#define NPTS    200000
#define NCH     32
#define RES     128
#define RR      (RES * RES)       // 16384
#define NPLANES 3
#define NBP     (BATCH * NPLANES) // 24
#define TOTPTS  (BATCH * NPTS)    // 1.6M

// Scratch (static __device__, allocation-free).
// featT: point-major features [b][n][c] so a bin's point reads are 128B contiguous.
__device__ __align__(128) float g_featT[(size_t)BATCH * NPTS * NCH];   // 205 MB
__device__ __align__(128) int   g_cnt[NBP * RR];      // zero at load; re-zeroed by gather
__device__ __align__(128) int   g_offs[NBP * RR];     // exclusive prefix (rewritten per call)
__device__ __align__(128) int   g_cursor[NBP * RR];   // bump cursors   (rewritten per call)
__device__ __align__(128) int   g_order[(size_t)NBP * NPTS];  // sorted point ids, 19.2 MB

// Bin math — mirrors reference exactly:
//   xyz_norm = (p+1)/2 - 0.5 ; u = xyz_norm/(1+eps) + 0.5 ; clip [0, 1-eps] ; floor(u*128)
__device__ __forceinline__ int bin_of(float v) {
    const float DEN  = 1.0f + 1e-5f;
    const float CLMP = 1.0f - 1e-5f;
    float u = ((v + 1.0f) * 0.5f - 0.5f) / DEN + 0.5f;
    u = fminf(fmaxf(u, 0.0f), CLMP);
    return (int)(u * (float)RES);
}

__device__ __forceinline__ void bins3(const float* __restrict__ xyz, int gid,
                                      int& lin0, int& lin1, int& lin2) {
    const float* p = xyz + (size_t)gid * 3;
    const int ix = bin_of(p[0]);
    const int iy = bin_of(p[1]);
    const int iz = bin_of(p[2]);
    lin0 = ix + RES * iy;   // xy
    lin1 = iy + RES * iz;   // yz
    lin2 = ix + RES * iz;   // xz
}

// ---------------------------------------------------------------------------
// K1: transpose feat (B,C,N) -> featT (B,N,C), fused with bin histogram.
// grid (NPTS/32, BATCH), block (32,8). Hist atomics hide under DRAM traffic.
// ---------------------------------------------------------------------------
__global__ void __launch_bounds__(256) transpose_hist_kernel(const float* __restrict__ xyz,
                                                             const float* __restrict__ feat) {
    __shared__ float tile[32][33];
    const int b  = blockIdx.y;
    const int n0 = blockIdx.x * 32;
    const int tx = threadIdx.x, ty = threadIdx.y;

#pragma unroll
    for (int i = 0; i < 4; i++) {
        const int c = ty + i * 8;
        tile[c][tx] = feat[((size_t)b * NCH + c) * NPTS + n0 + tx];   // coalesced in n
    }
    __syncthreads();
#pragma unroll
    for (int i = 0; i < 4; i++) {
        const int row = ty + i * 8;
        g_featT[((size_t)b * NPTS + n0 + row) * NCH + tx] = tile[tx][row];  // coalesced in c
    }

    // Fused histogram: flat thread id over all blocks covers all points once.
    const int t = (blockIdx.y * gridDim.x + blockIdx.x) * 256 + ty * 32 + tx;
    if (t < TOTPTS) {
        const int pb = t / NPTS;
        int lin0, lin1, lin2;
        bins3(xyz, t, lin0, lin1, lin2);
        const int bp = pb * NPLANES;
        atomicAdd(&g_cnt[(bp + 0) * RR + lin0], 1);
        atomicAdd(&g_cnt[(bp + 1) * RR + lin1], 1);
        atomicAdd(&g_cnt[(bp + 2) * RR + lin2], 1);
    }
}

// ---------------------------------------------------------------------------
// K2: exclusive scan of counts within each (b,plane). 24 blocks x 1024 threads,
// 16 elements per thread; Hillis-Steele block scan of per-thread sums.
// ---------------------------------------------------------------------------
__global__ void __launch_bounds__(1024) scan_kernel() {
    __shared__ int ssum[1024];
    const int bp = blockIdx.x;
    const int t  = threadIdx.x;
    const int base = bp * RR + t * 16;

    int local[16];
    int s = 0;
#pragma unroll
    for (int i = 0; i < 16; i++) { local[i] = g_cnt[base + i]; s += local[i]; }
    ssum[t] = s;
    __syncthreads();

    for (int off = 1; off < 1024; off <<= 1) {
        int v = (t >= off) ? ssum[t - off] : 0;
        __syncthreads();
        ssum[t] += v;
        __syncthreads();
    }

    int run = (t > 0) ? ssum[t - 1] : 0;   // exclusive prefix of this thread's chunk
#pragma unroll
    for (int i = 0; i < 16; i++) {
        g_offs[base + i]   = run;
        g_cursor[base + i] = run;
        run += local[i];
    }
}

// ---------------------------------------------------------------------------
// K3: scatter point ids into sorted order via bump cursors.
// ---------------------------------------------------------------------------
__global__ void __launch_bounds__(256) scatter_idx_kernel(const float* __restrict__ xyz) {
    const int gid = blockIdx.x * 256 + threadIdx.x;
    if (gid >= TOTPTS) return;
    const int b = gid / NPTS;
    const int n = gid - b * NPTS;

    int lin[3];
    bins3(xyz, gid, lin[0], lin[1], lin[2]);
    const int bp = b * NPLANES;
#pragma unroll
    for (int pl = 0; pl < NPLANES; pl++) {
        const int pos = atomicAdd(&g_cursor[(bp + pl) * RR + lin[pl]], 1);
        g_order[(size_t)(bp + pl) * NPTS + pos] = n;
    }
}

// ---------------------------------------------------------------------------
// K4: atomic-free segmented reduce + output write.
// Block = 256 (8 warps) covers 32 consecutive bins of one (b,plane); each warp
// reduces 4 bins serially (lane = channel, register accumulator). Results are
// staged in padded smem and written transposed+coalesced. Re-zeros g_cnt.
// ---------------------------------------------------------------------------
__global__ void __launch_bounds__(256) gather_kernel(float* __restrict__ out) {
    __shared__ float s[32][33];

    const int tiles_per_bp = RR / 32;                 // 512
    const int bp   = blockIdx.x / tiles_per_bp;       // 0..23
    const int tile = blockIdx.x % tiles_per_bp;
    const int bin0 = tile * 32;
    const int w    = threadIdx.x >> 5;                // warp 0..7
    const int lane = threadIdx.x & 31;                // channel
    const int b    = bp / NPLANES;

    const int*   order = g_order + (size_t)bp * NPTS;
    const float* ft    = g_featT + (size_t)b * NPTS * NCH;

#pragma unroll
    for (int j = 0; j < 4; j++) {
        const int binLocal = j * 8 + w;
        const int bin = bin0 + binLocal;
        const int start = g_offs[bp * RR + bin];
        const int k     = g_cnt[bp * RR + bin];

        float sum = 0.0f;
        int i = 0;
        for (; i + 2 <= k; i += 2) {                  // unroll 2: independent loads
            const int n0 = order[start + i];
            const int n1 = order[start + i + 1];
            const float v0 = ft[(size_t)n0 * NCH + lane];
            const float v1 = ft[(size_t)n1 * NCH + lane];
            sum += v0;
            sum += v1;
        }
        if (i < k) {
            const int n0 = order[start + i];
            sum += ft[(size_t)n0 * NCH + lane];
        }

        const float inv = 1.0f / (float)max(k, 1);
        s[binLocal][lane] = sum * inv;
        if (lane == 0) g_cnt[bp * RR + bin] = 0;      // restore zero-invariant
    }
    __syncthreads();

    // Coalesced output write: out[(bp*C + c)*RR + bin0 + i]
    float* ob = out + (size_t)bp * NCH * RR + bin0;
    for (int jj = threadIdx.x; jj < 32 * NCH; jj += 256) {
        const int c = jj >> 5;       // channel
        const int i = jj & 31;       // bin within tile
        ob[(size_t)c * RR + i] = s[i][c];
    }
}

// ---------------------------------------------------------------------------
extern "C" void kernel_launch(void* const* d_in, const int* in_sizes, int n_in,
                              void* d_out, int out_size) {
    const float* xyz  = (const float*)d_in[0];  // (B, N, 3)
    const float* feat = (const float*)d_in[1];  // (B, C, N)
    float* out = (float*)d_out;                 // (B, 3, C, R, R)

    dim3 g1(NPTS / 32, BATCH), b1(32, 8);
    transpose_hist_kernel<<<g1, b1>>>(xyz, feat);

    scan_kernel<<<NBP, 1024>>>();

    scatter_idx_kernel<<<(TOTPTS + 255) / 256, 256>>>(xyz);

    gather_kernel<<<NBP * (RR / 32), 256>>>(out);
}

// round 5
// speedup vs baseline: 1.9117x; 1.9016x over previous
#include <cuda_runtime.h>
#include <cstdint>

// Problem constants
#define BATCH   8
#define NPTS    200000
#define NCH     32
#define RES     128
#define RR      (RES * RES)       // 16384
#define NPLANES 3
#define NBP     (BATCH * NPLANES) // 24
#define TOTPTS  (BATCH * NPTS)    // 1.6M

// Scratch (static __device__, allocation-free).
// featT: point-major features [b][n][c] so a bin's point reads are 128B contiguous.
__device__ __align__(128) float g_featT[(size_t)BATCH * NPTS * NCH];   // 205 MB
__device__ __align__(128) int   g_cnt[NBP * RR];      // zero at load; re-zeroed by gather
__device__ __align__(128) int   g_offs[NBP * RR];     // exclusive prefix (rewritten per call)
__device__ __align__(128) int   g_cursor[NBP * RR];   // bump cursors   (rewritten per call)
__device__ __align__(128) int   g_order[(size_t)NBP * NPTS];  // sorted point ids, 19.2 MB

// Bin math — mirrors reference exactly:
//   xyz_norm = (p+1)/2 - 0.5 ; u = xyz_norm/(1+eps) + 0.5 ; clip [0, 1-eps] ; floor(u*128)
__device__ __forceinline__ int bin_of(float v) {
    const float DEN  = 1.0f + 1e-5f;
    const float CLMP = 1.0f - 1e-5f;
    float u = ((v + 1.0f) * 0.5f - 0.5f) / DEN + 0.5f;
    u = fminf(fmaxf(u, 0.0f), CLMP);
    return (int)(u * (float)RES);
}

__device__ __forceinline__ void bins3(const float* __restrict__ xyz, int gid,
                                      int& lin0, int& lin1, int& lin2) {
    const float* p = xyz + (size_t)gid * 3;
    const int ix = bin_of(p[0]);
    const int iy = bin_of(p[1]);
    const int iz = bin_of(p[2]);
    lin0 = ix + RES * iy;   // xy
    lin1 = iy + RES * iz;   // yz
    lin2 = ix + RES * iz;   // xz
}

// ---------------------------------------------------------------------------
// K1: transpose feat (B,C,N) -> featT (B,N,C), fused with bin histogram.
// ---------------------------------------------------------------------------
__global__ void __launch_bounds__(256) transpose_hist_kernel(const float* __restrict__ xyz,
                                                             const float* __restrict__ feat) {
    __shared__ float tile[32][33];
    const int b  = blockIdx.y;
    const int n0 = blockIdx.x * 32;
    const int tx = threadIdx.x, ty = threadIdx.y;

#pragma unroll
    for (int i = 0; i < 4; i++) {
        const int c = ty + i * 8;
        tile[c][tx] = feat[((size_t)b * NCH + c) * NPTS + n0 + tx];   // coalesced in n
    }
    __syncthreads();
#pragma unroll
    for (int i = 0; i < 4; i++) {
        const int row = ty + i * 8;
        g_featT[((size_t)b * NPTS + n0 + row) * NCH + tx] = tile[tx][row];  // coalesced in c
    }

    // Fused histogram: flat thread id over all blocks covers all points once.
    const int t = (blockIdx.y * gridDim.x + blockIdx.x) * 256 + ty * 32 + tx;
    if (t < TOTPTS) {
        const int pb = t / NPTS;
        int lin0, lin1, lin2;
        bins3(xyz, t, lin0, lin1, lin2);
        const int bp = pb * NPLANES;
        atomicAdd(&g_cnt[(bp + 0) * RR + lin0], 1);
        atomicAdd(&g_cnt[(bp + 1) * RR + lin1], 1);
        atomicAdd(&g_cnt[(bp + 2) * RR + lin2], 1);
    }
}

// ---------------------------------------------------------------------------
// K2: exclusive scan of counts within each (b,plane). 24 blocks x 1024 threads.
// ---------------------------------------------------------------------------
__global__ void __launch_bounds__(1024) scan_kernel() {
    __shared__ int ssum[1024];
    const int bp = blockIdx.x;
    const int t  = threadIdx.x;
    const int base = bp * RR + t * 16;

    int local[16];
    int s = 0;
#pragma unroll
    for (int i = 0; i < 16; i++) { local[i] = g_cnt[base + i]; s += local[i]; }
    ssum[t] = s;
    __syncthreads();

    for (int off = 1; off < 1024; off <<= 1) {
        int v = (t >= off) ? ssum[t - off] : 0;
        __syncthreads();
        ssum[t] += v;
        __syncthreads();
    }

    int run = (t > 0) ? ssum[t - 1] : 0;
#pragma unroll
    for (int i = 0; i < 16; i++) {
        g_offs[base + i]   = run;
        g_cursor[base + i] = run;
        run += local[i];
    }
}

// ---------------------------------------------------------------------------
// K3: scatter point ids into sorted order via bump cursors.
// ---------------------------------------------------------------------------
__global__ void __launch_bounds__(256) scatter_idx_kernel(const float* __restrict__ xyz) {
    const int gid = blockIdx.x * 256 + threadIdx.x;
    if (gid >= TOTPTS) return;
    const int b = gid / NPTS;
    const int n = gid - b * NPTS;

    int lin[3];
    bins3(xyz, gid, lin[0], lin[1], lin[2]);
    const int bp = b * NPLANES;
#pragma unroll
    for (int pl = 0; pl < NPLANES; pl++) {
        const int pos = atomicAdd(&g_cursor[(bp + pl) * RR + lin[pl]], 1);
        g_order[(size_t)(bp + pl) * NPTS + pos] = n;
    }
}

// ---------------------------------------------------------------------------
// K4: atomic-free segmented reduce, POINT-PARALLEL within each warp.
// Warp per bin (4 bins/warp serially): lane = p*8+cq; lane loads float4 of
// channels [cq*4..cq*4+3] for point slot p. Two accumulators -> 8 independent
// 16B loads in flight per warp. Cross-p shfl reduce at the end.
// Block index is (batch-major, tile, plane) so the 3 planes of one batch run
// concurrently and featT stays L2-resident per batch (25.6 MB << 126 MB L2).
// ---------------------------------------------------------------------------
__global__ void __launch_bounds__(256) gather_kernel(float* __restrict__ out) {
    __shared__ float s[32][33];

    const int tiles_per_bp = RR / 32;                    // 512
    const int blk  = blockIdx.x;
    const int b    = blk / (NPLANES * tiles_per_bp);     // batch-major
    const int r    = blk - b * (NPLANES * tiles_per_bp);
    const int tile = r / NPLANES;
    const int pl   = r - tile * NPLANES;
    const int bp   = b * NPLANES + pl;
    const int bin0 = tile * 32;

    const int w    = threadIdx.x >> 5;                   // warp 0..7
    const int lane = threadIdx.x & 31;
    const int p    = lane >> 3;                          // point slot 0..3
    const int cq   = lane & 7;                           // channel quad 0..7

    const int*    order = g_order + (size_t)bp * NPTS;
    const float4* ftv   = reinterpret_cast<const float4*>(g_featT + (size_t)b * NPTS * NCH);

#pragma unroll
    for (int j = 0; j < 4; j++) {
        const int binLocal = j * 8 + w;
        const int bin   = bin0 + binLocal;
        const int start = g_offs[bp * RR + bin];
        const int k     = g_cnt[bp * RR + bin];

        float4 a0 = {0.f, 0.f, 0.f, 0.f};
        float4 a1 = {0.f, 0.f, 0.f, 0.f};
        for (int i = 0; i < k; i += 8) {
            const int i0 = i + p;
            const int i1 = i + 4 + p;
            if (i0 < k) {
                const int n = order[start + i0];
                const float4 v = ftv[(size_t)n * 8 + cq];
                a0.x += v.x; a0.y += v.y; a0.z += v.z; a0.w += v.w;
            }
            if (i1 < k) {
                const int n = order[start + i1];
                const float4 v = ftv[(size_t)n * 8 + cq];
                a1.x += v.x; a1.y += v.y; a1.z += v.z; a1.w += v.w;
            }
        }
        a0.x += a1.x; a0.y += a1.y; a0.z += a1.z; a0.w += a1.w;

        // reduce across point slots p (lanes cq, cq+8, cq+16, cq+24)
#pragma unroll
        for (int off = 8; off <= 16; off <<= 1) {
            a0.x += __shfl_xor_sync(0xffffffffu, a0.x, off);
            a0.y += __shfl_xor_sync(0xffffffffu, a0.y, off);
            a0.z += __shfl_xor_sync(0xffffffffu, a0.z, off);
            a0.w += __shfl_xor_sync(0xffffffffu, a0.w, off);
        }

        if (p == 0) {
            const float inv = 1.0f / (float)max(k, 1);
            s[binLocal][cq * 4 + 0] = a0.x * inv;
            s[binLocal][cq * 4 + 1] = a0.y * inv;
            s[binLocal][cq * 4 + 2] = a0.z * inv;
            s[binLocal][cq * 4 + 3] = a0.w * inv;
        }
        if (lane == 0) g_cnt[bp * RR + bin] = 0;          // restore zero-invariant
    }
    __syncthreads();

    // Coalesced output write: out[(bp*C + c)*RR + bin0 + i]
    float* ob = out + (size_t)bp * NCH * RR + bin0;
    for (int jj = threadIdx.x; jj < 32 * NCH; jj += 256) {
        const int c = jj >> 5;       // channel
        const int i = jj & 31;       // bin within tile
        ob[(size_t)c * RR + i] = s[i][c];
    }
}

// ---------------------------------------------------------------------------
extern "C" void kernel_launch(void* const* d_in, const int* in_sizes, int n_in,
                              void* d_out, int out_size) {
    const float* xyz  = (const float*)d_in[0];  // (B, N, 3)
    const float* feat = (const float*)d_in[1];  // (B, C, N)
    float* out = (float*)d_out;                 // (B, 3, C, R, R)

    dim3 g1(NPTS / 32, BATCH), b1(32, 8);
    transpose_hist_kernel<<<g1, b1>>>(xyz, feat);

    scan_kernel<<<NBP, 1024>>>();

    scatter_idx_kernel<<<(TOTPTS + 255) / 256, 256>>>(xyz);

    gather_kernel<<<NBP * (RR / 32), 256>>>(out);
}

// round 7
// speedup vs baseline: 2.2526x; 1.1783x over previous
#include <cuda_runtime.h>
#include <cstdint>

// Problem constants
#define BATCH   8
#define NPTS    200000
#define NCH     32
#define RES     128
#define RR      (RES * RES)       // 16384
#define NPLANES 3
#define NBP     (BATCH * NPLANES) // 24
#define TOTPTS  (BATCH * NPTS)    // 1.6M

// Scratch (static __device__, allocation-free).
__device__ __align__(128) float g_featT[(size_t)BATCH * NPTS * NCH];   // 205 MB
__device__ __align__(128) int   g_cnt[NBP * RR];      // zero at load; re-zeroed by gather
__device__ __align__(128) int   g_offs[NBP * RR];
__device__ __align__(128) int   g_cursor[NBP * RR];
__device__ __align__(128) int   g_order[(size_t)NBP * NPTS];  // sorted point ids

// Bin math — mirrors reference exactly.
__device__ __forceinline__ int bin_of(float v) {
    const float DEN  = 1.0f + 1e-5f;
    const float CLMP = 1.0f - 1e-5f;
    float u = ((v + 1.0f) * 0.5f - 0.5f) / DEN + 0.5f;
    u = fminf(fmaxf(u, 0.0f), CLMP);
    return (int)(u * (float)RES);
}

__device__ __forceinline__ void bins3(const float* __restrict__ xyz, int gid,
                                      int& lin0, int& lin1, int& lin2) {
    const float* p = xyz + (size_t)gid * 3;
    const int ix = bin_of(p[0]);
    const int iy = bin_of(p[1]);
    const int iz = bin_of(p[2]);
    lin0 = ix + RES * iy;   // xy
    lin1 = iy + RES * iz;   // yz
    lin2 = ix + RES * iz;   // xz
}

// ---------------------------------------------------------------------------
// K1: transpose feat (B,C,N) -> featT (B,N,C), fused with bin histogram.
// ---------------------------------------------------------------------------
__global__ void __launch_bounds__(256) transpose_hist_kernel(const float* __restrict__ xyz,
                                                             const float* __restrict__ feat) {
    __shared__ float tile[32][33];
    const int b  = blockIdx.y;
    const int n0 = blockIdx.x * 32;
    const int tx = threadIdx.x, ty = threadIdx.y;

#pragma unroll
    for (int i = 0; i < 4; i++) {
        const int c = ty + i * 8;
        tile[c][tx] = feat[((size_t)b * NCH + c) * NPTS + n0 + tx];   // coalesced in n
    }
    __syncthreads();
#pragma unroll
    for (int i = 0; i < 4; i++) {
        const int row = ty + i * 8;
        g_featT[((size_t)b * NPTS + n0 + row) * NCH + tx] = tile[tx][row];  // coalesced in c
    }

    // Fused histogram: flat thread id over all blocks covers all points once.
    const int t = (blockIdx.y * gridDim.x + blockIdx.x) * 256 + ty * 32 + tx;
    if (t < TOTPTS) {
        const int pb = t / NPTS;
        int lin0, lin1, lin2;
        bins3(xyz, t, lin0, lin1, lin2);
        const int bp = pb * NPLANES;
        atomicAdd(&g_cnt[(bp + 0) * RR + lin0], 1);
        atomicAdd(&g_cnt[(bp + 1) * RR + lin1], 1);
        atomicAdd(&g_cnt[(bp + 2) * RR + lin2], 1);
    }
}

// ---------------------------------------------------------------------------
// K2: exclusive scan of counts within each (b,plane). 24 blocks x 1024 threads.
// ---------------------------------------------------------------------------
__global__ void __launch_bounds__(1024) scan_kernel() {
    __shared__ int ssum[1024];
    const int bp = blockIdx.x;
    const int t  = threadIdx.x;
    const int base = bp * RR + t * 16;

    int local[16];
    int s = 0;
#pragma unroll
    for (int i = 0; i < 16; i++) { local[i] = g_cnt[base + i]; s += local[i]; }
    ssum[t] = s;
    __syncthreads();

    for (int off = 1; off < 1024; off <<= 1) {
        int v = (t >= off) ? ssum[t - off] : 0;
        __syncthreads();
        ssum[t] += v;
        __syncthreads();
    }

    int run = (t > 0) ? ssum[t - 1] : 0;
#pragma unroll
    for (int i = 0; i < 16; i++) {
        g_offs[base + i]   = run;
        g_cursor[base + i] = run;
        run += local[i];
    }
}

// ---------------------------------------------------------------------------
// K3: scatter point ids into sorted order via bump cursors.
// ---------------------------------------------------------------------------
__global__ void __launch_bounds__(256) scatter_idx_kernel(const float* __restrict__ xyz) {
    const int gid = blockIdx.x * 256 + threadIdx.x;
    if (gid >= TOTPTS) return;
    const int b = gid / NPTS;
    const int n = gid - b * NPTS;

    int lin[3];
    bins3(xyz, gid, lin[0], lin[1], lin[2]);
    const int bp = b * NPLANES;
#pragma unroll
    for (int pl = 0; pl < NPLANES; pl++) {
        const int pos = atomicAdd(&g_cursor[(bp + pl) * RR + lin[pl]], 1);
        g_order[(size_t)(bp + pl) * NPTS + pos] = n;
    }
}

// ---------------------------------------------------------------------------
// K4: atomic-free segmented reduce, INDEX-FIRST.
// Warp per bin (4 bins/warp serially). Step 1: one coalesced 32-lane load of
// order[start..start+31] into registers (covers avg k=12; chunk loop for
// k>32). Step 2: feature loads get their index via shfl from registers, so
// every featT load in a bin is independent -> MLP = ceil(k/4) per lane with
// NO load-load dependency. Lane = p*8+cq: slot p covers points i+p, cq picks
// the float4 of channels [cq*4 .. cq*4+3]. Cross-p shfl-xor reduce at end.
// Batch-major block order keeps featT L2-resident per batch.
// ---------------------------------------------------------------------------
__global__ void __launch_bounds__(256) gather_kernel(float* __restrict__ out) {
    __shared__ float s[32][33];

    const int tiles_per_bp = RR / 32;                    // 512
    const int blk  = blockIdx.x;
    const int b    = blk / (NPLANES * tiles_per_bp);     // batch-major
    const int r    = blk - b * (NPLANES * tiles_per_bp);
    const int tile = r / NPLANES;
    const int pl   = r - tile * NPLANES;
    const int bp   = b * NPLANES + pl;
    const int bin0 = tile * 32;

    const int w    = threadIdx.x >> 5;                   // warp 0..7
    const int lane = threadIdx.x & 31;
    const int p    = lane >> 3;                          // point slot 0..3
    const int cq   = lane & 7;                           // channel quad 0..7

    const int*    order = g_order + (size_t)bp * NPTS;
    const float4* ftv   = reinterpret_cast<const float4*>(g_featT + (size_t)b * NPTS * NCH);

    // Prefetch all 4 bins' metadata up front (independent loads).
    int starts[4], ks[4];
#pragma unroll
    for (int j = 0; j < 4; j++) {
        const int bin = bin0 + j * 8 + w;
        starts[j] = g_offs[bp * RR + bin];
        ks[j]     = g_cnt[bp * RR + bin];
    }

#pragma unroll
    for (int j = 0; j < 4; j++) {
        const int binLocal = j * 8 + w;
        const int start = starts[j];
        const int k     = ks[j];

        float4 acc = {0.f, 0.f, 0.f, 0.f};
        for (int base = 0; base < k; base += 32) {
            const int m = min(32, k - base);
            int idxv = 0;
            if (lane < m) idxv = order[start + base + lane];   // coalesced 128B

#pragma unroll 4
            for (int i = 0; i < m; i += 4) {
                const int slot = i + p;
                const int n = __shfl_sync(0xffffffffu, idxv, slot & 31);
                if (slot < m) {
                    const float4 v = ftv[(size_t)n * 8 + cq];
                    acc.x += v.x; acc.y += v.y; acc.z += v.z; acc.w += v.w;
                }
            }
        }

        // reduce across point slots p (lanes cq, cq+8, cq+16, cq+24)
#pragma unroll
        for (int off = 8; off <= 16; off <<= 1) {
            acc.x += __shfl_xor_sync(0xffffffffu, acc.x, off);
            acc.y += __shfl_xor_sync(0xffffffffu, acc.y, off);
            acc.z += __shfl_xor_sync(0xffffffffu, acc.z, off);
            acc.w += __shfl_xor_sync(0xffffffffu, acc.w, off);
        }

        if (p == 0) {
            const float inv = 1.0f / (float)max(k, 1);
            s[binLocal][cq * 4 + 0] = acc.x * inv;
            s[binLocal][cq * 4 + 1] = acc.y * inv;
            s[binLocal][cq * 4 + 2] = acc.z * inv;
            s[binLocal][cq * 4 + 3] = acc.w * inv;
        }
        if (lane == 0) g_cnt[bp * RR + bin0 + binLocal] = 0;   // restore zero-invariant
    }
    __syncthreads();

    // Coalesced output write: out[(bp*C + c)*RR + bin0 + i]
    float* ob = out + (size_t)bp * NCH * RR + bin0;
    for (int jj = threadIdx.x; jj < 32 * NCH; jj += 256) {
        const int c = jj >> 5;       // channel
        const int i = jj & 31;       // bin within tile
        ob[(size_t)c * RR + i] = s[i][c];
    }
}

// ---------------------------------------------------------------------------
extern "C" void kernel_launch(void* const* d_in, const int* in_sizes, int n_in,
                              void* d_out, int out_size) {
    const float* xyz  = (const float*)d_in[0];  // (B, N, 3)
    const float* feat = (const float*)d_in[1];  // (B, C, N)
    float* out = (float*)d_out;                 // (B, 3, C, R, R)

    dim3 g1(NPTS / 32, BATCH), b1(32, 8);
    transpose_hist_kernel<<<g1, b1>>>(xyz, feat);

    scan_kernel<<<NBP, 1024>>>();

    scatter_idx_kernel<<<(TOTPTS + 255) / 256, 256>>>(xyz);

    gather_kernel<<<NBP * (RR / 32), 256>>>(out);
}

// round 13
// speedup vs baseline: 2.7835x; 1.2356x over previous
#include <cuda_runtime.h>
#include <cuda_fp16.h>
#include <cstdint>

// Problem constants
#define BATCH   8
#define NPTS    200000
#define NCH     32
#define RES     128
#define RR      (RES * RES)       // 16384
#define NPLANES 3
#define NBP     (BATCH * NPLANES) // 24
#define TOTPTS  (BATCH * NPTS)    // 1.6M

// Scratch (static __device__, allocation-free).
// featT: point-major fp16 features [b][n][c] (64B per point).
__device__ __align__(128) __half g_featT[(size_t)BATCH * NPTS * NCH];  // 102 MB
__device__ __align__(128) int    g_cnt[NBP * RR];     // zero at load; re-zeroed by gather
__device__ __align__(128) int    g_offs[NBP * RR];
__device__ __align__(128) int    g_cursor[NBP * RR];
__device__ __align__(128) int    g_order[(size_t)NBP * NPTS];  // sorted point ids

// Bin math — mirrors reference exactly.
__device__ __forceinline__ int bin_of(float v) {
    const float DEN  = 1.0f + 1e-5f;
    const float CLMP = 1.0f - 1e-5f;
    float u = ((v + 1.0f) * 0.5f - 0.5f) / DEN + 0.5f;
    u = fminf(fmaxf(u, 0.0f), CLMP);
    return (int)(u * (float)RES);
}

__device__ __forceinline__ void bins3(const float* __restrict__ xyz, int gid,
                                      int& lin0, int& lin1, int& lin2) {
    const float* p = xyz + (size_t)gid * 3;
    const int ix = bin_of(p[0]);
    const int iy = bin_of(p[1]);
    const int iz = bin_of(p[2]);
    lin0 = ix + RES * iy;   // xy
    lin1 = iy + RES * iz;   // yz
    lin2 = ix + RES * iz;   // xz
}

// ---------------------------------------------------------------------------
// K1: transpose feat (B,C,N) fp32 -> featT (B,N,C) fp16, fused with histogram.
// ---------------------------------------------------------------------------
__global__ void __launch_bounds__(256) transpose_hist_kernel(const float* __restrict__ xyz,
                                                             const float* __restrict__ feat) {
    __shared__ float tile[32][33];
    const int b  = blockIdx.y;
    const int n0 = blockIdx.x * 32;
    const int tx = threadIdx.x, ty = threadIdx.y;

#pragma unroll
    for (int i = 0; i < 4; i++) {
        const int c = ty + i * 8;
        tile[c][tx] = feat[((size_t)b * NCH + c) * NPTS + n0 + tx];   // coalesced in n
    }
    __syncthreads();
#pragma unroll
    for (int i = 0; i < 4; i++) {
        const int row = ty + i * 8;
        g_featT[((size_t)b * NPTS + n0 + row) * NCH + tx] =
            __float2half(tile[tx][row]);                              // coalesced in c
    }

    // Fused histogram: flat thread id over all blocks covers all points once.
    const int t = (blockIdx.y * gridDim.x + blockIdx.x) * 256 + ty * 32 + tx;
    if (t < TOTPTS) {
        const int pb = t / NPTS;
        int lin0, lin1, lin2;
        bins3(xyz, t, lin0, lin1, lin2);
        const int bp = pb * NPLANES;
        atomicAdd(&g_cnt[(bp + 0) * RR + lin0], 1);
        atomicAdd(&g_cnt[(bp + 1) * RR + lin1], 1);
        atomicAdd(&g_cnt[(bp + 2) * RR + lin2], 1);
    }
}

// ---------------------------------------------------------------------------
// K2: exclusive scan of counts within each (b,plane). 24 blocks x 1024 threads.
// ---------------------------------------------------------------------------
__global__ void __launch_bounds__(1024) scan_kernel() {
    __shared__ int ssum[1024];
    const int bp = blockIdx.x;
    const int t  = threadIdx.x;
    const int base = bp * RR + t * 16;

    int local[16];
    int s = 0;
#pragma unroll
    for (int i = 0; i < 16; i++) { local[i] = g_cnt[base + i]; s += local[i]; }
    ssum[t] = s;
    __syncthreads();

    for (int off = 1; off < 1024; off <<= 1) {
        int v = (t >= off) ? ssum[t - off] : 0;
        __syncthreads();
        ssum[t] += v;
        __syncthreads();
    }

    int run = (t > 0) ? ssum[t - 1] : 0;
#pragma unroll
    for (int i = 0; i < 16; i++) {
        g_offs[base + i]   = run;
        g_cursor[base + i] = run;
        run += local[i];
    }
}

// ---------------------------------------------------------------------------
// K3: scatter point ids into sorted order via bump cursors.
// ---------------------------------------------------------------------------
__global__ void __launch_bounds__(256) scatter_idx_kernel(const float* __restrict__ xyz) {
    const int gid = blockIdx.x * 256 + threadIdx.x;
    if (gid >= TOTPTS) return;
    const int b = gid / NPTS;
    const int n = gid - b * NPTS;

    int lin[3];
    bins3(xyz, gid, lin[0], lin[1], lin[2]);
    const int bp = b * NPLANES;
#pragma unroll
    for (int pl = 0; pl < NPLANES; pl++) {
        const int pos = atomicAdd(&g_cursor[(bp + pl) * RR + lin[pl]], 1);
        g_order[(size_t)(bp + pl) * NPTS + pos] = n;
    }
}

// ---------------------------------------------------------------------------
// K4: atomic-free segmented reduce, index-first + cross-bin decoupling.
// Warp per bin x4. Index loads for ALL 4 bins issued up front (independent,
// coalesced); indices then distributed by shfl, so feature loads are fully
// independent within and across bins. Lane = p*8+cq: point slot p (0..3),
// channel quad cq (0..7, 8B fp16 = 4 channels). fp32 accumulation.
// Batch-major block order keeps featT (12.8 MB/batch) L2-resident.
// ---------------------------------------------------------------------------
__global__ void __launch_bounds__(256) gather_kernel(float* __restrict__ out) {
    __shared__ float s[32][33];

    const int tiles_per_bp = RR / 32;                    // 512
    const int blk  = blockIdx.x;
    const int b    = blk / (NPLANES * tiles_per_bp);     // batch-major
    const int r    = blk - b * (NPLANES * tiles_per_bp);
    const int tile = r / NPLANES;
    const int pl   = r - tile * NPLANES;
    const int bp   = b * NPLANES + pl;
    const int bin0 = tile * 32;

    const int w    = threadIdx.x >> 5;                   // warp 0..7
    const int lane = threadIdx.x & 31;
    const int p    = lane >> 3;                          // point slot 0..3
    const int cq   = lane & 7;                           // channel quad 0..7

    const int*   order = g_order + (size_t)bp * NPTS;
    const uint2* ftv   = reinterpret_cast<const uint2*>(g_featT + (size_t)b * NPTS * NCH);

    // Prefetch all 4 bins' metadata, then all 4 bins' first index chunk
    // (4 independent coalesced loads in flight before any feature work).
    int starts[4], ks[4];
#pragma unroll
    for (int j = 0; j < 4; j++) {
        const int bin = bin0 + j * 8 + w;
        starts[j] = g_offs[bp * RR + bin];
        ks[j]     = g_cnt[bp * RR + bin];
    }
    int idx0[4];
#pragma unroll
    for (int j = 0; j < 4; j++) {
        const int m = min(ks[j], 32);
        idx0[j] = (lane < m) ? order[starts[j] + lane] : 0;
    }

#pragma unroll
    for (int j = 0; j < 4; j++) {
        const int binLocal = j * 8 + w;
        const int k = ks[j];

        float4 acc = {0.f, 0.f, 0.f, 0.f};

        const int m0 = min(k, 32);
        for (int i = 0; i < m0; i += 4) {
            const int slot = i + p;
            const int n = __shfl_sync(0xffffffffu, idx0[j], slot & 31);
            if (slot < m0) {
                const uint2 v = ftv[(size_t)n * 8 + cq];
                const float2 f0 = __half22float2(*reinterpret_cast<const __half2*>(&v.x));
                const float2 f1 = __half22float2(*reinterpret_cast<const __half2*>(&v.y));
                acc.x += f0.x; acc.y += f0.y; acc.z += f1.x; acc.w += f1.y;
            }
        }
        // Rare spill: bins with k > 32.
        for (int base = 32; base < k; base += 32) {
            const int m = min(32, k - base);
            int idxv = 0;
            if (lane < m) idxv = order[starts[j] + base + lane];
            for (int i = 0; i < m; i += 4) {
                const int slot = i + p;
                const int n = __shfl_sync(0xffffffffu, idxv, slot & 31);
                if (slot < m) {
                    const uint2 v = ftv[(size_t)n * 8 + cq];
                    const float2 f0 = __half22float2(*reinterpret_cast<const __half2*>(&v.x));
                    const float2 f1 = __half22float2(*reinterpret_cast<const __half2*>(&v.y));
                    acc.x += f0.x; acc.y += f0.y; acc.z += f1.x; acc.w += f1.y;
                }
            }
        }

        // reduce across point slots p (lanes cq, cq+8, cq+16, cq+24)
#pragma unroll
        for (int off = 8; off <= 16; off <<= 1) {
            acc.x += __shfl_xor_sync(0xffffffffu, acc.x, off);
            acc.y += __shfl_xor_sync(0xffffffffu, acc.y, off);
            acc.z += __shfl_xor_sync(0xffffffffu, acc.z, off);
            acc.w += __shfl_xor_sync(0xffffffffu, acc.w, off);
        }

        if (p == 0) {
            const float inv = 1.0f / (float)max(k, 1);
            s[binLocal][cq * 4 + 0] = acc.x * inv;
            s[binLocal][cq * 4 + 1] = acc.y * inv;
            s[binLocal][cq * 4 + 2] = acc.z * inv;
            s[binLocal][cq * 4 + 3] = acc.w * inv;
        }
        if (lane == 0) g_cnt[bp * RR + bin0 + binLocal] = 0;   // restore zero-invariant
    }
    __syncthreads();

    // Coalesced output write: out[(bp*C + c)*RR + bin0 + i]
    float* ob = out + (size_t)bp * NCH * RR + bin0;
    for (int jj = threadIdx.x; jj < 32 * NCH; jj += 256) {
        const int c = jj >> 5;       // channel
        const int i = jj & 31;       // bin within tile
        ob[(size_t)c * RR + i] = s[i][c];
    }
}

// ---------------------------------------------------------------------------
extern "C" void kernel_launch(void* const* d_in, const int* in_sizes, int n_in,
                              void* d_out, int out_size) {
    const float* xyz  = (const float*)d_in[0];  // (B, N, 3)
    const float* feat = (const float*)d_in[1];  // (B, C, N)
    float* out = (float*)d_out;                 // (B, 3, C, R, R)

    dim3 g1(NPTS / 32, BATCH), b1(32, 8);
    transpose_hist_kernel<<<g1, b1>>>(xyz, feat);

    scan_kernel<<<NBP, 1024>>>();

    scatter_idx_kernel<<<(TOTPTS + 255) / 256, 256>>>(xyz);

    gather_kernel<<<NBP * (RR / 32), 256>>>(out);
}